// round 7
// baseline (speedup 1.0000x reference)
#include <cuda_runtime.h>
#include <stdint.h>

// Algebraic feature expansion:
//   out[:, 0:16]    = x
//   out[:, 16:136]  = pair products  x[a]*x[b]   (lex order)
//   out[:, 136:696] = triple products x[a]*x[b]*x[c] (lex order)
// B=262144 rows, 696 out cols. HBM-store-bound (~730 MB out).
//
// v7: exact v2 structure (best known: full 16-row unroll, no reg cap,
// pointer-decoded operand indices, grid 1480), with two store-path tweaks:
//   - plain stores instead of __stcs: rows are 2784 B (not a 128B multiple),
//     so stores straddle sectors shared with neighbors; default eviction lets
//     L2 merge the seams into full-sector writebacks (evict-first risked
//     partial-sector DRAM writes -> read-modify-write).
//   - dummy col-16 (=1.0) written once, outside the tile loop.

#define NC    16
#define NPAIR 120
#define OUTC  696
#define Q4    174          // OUTC / 4
#define RTILE 16           // rows per tile
#define PAD   20           // floats per cached row (16 data + 1.0 dummy + align)
#define BLK   192          // 6 warps; threads [0,174) compute

__global__ __launch_bounds__(BLK) void algebraic_expand_kernel(
    const float* __restrict__ x,
    float4* __restrict__ out4,
    int nrows)
{
    __shared__ __align__(16) uint32_t stab[OUTC];
    __shared__ __align__(16) float xs[RTILE][PAD];

    const int t = threadIdx.x;

    // ---- Build packed index table once (a | b<<8 | c<<16; 16 = dummy -> 1.0) ----
    for (int col = t; col < OUTC; col += BLK) {
        int a, b, c;
        if (col < NC) {
            a = col; b = 16; c = 16;
        } else if (col < NC + NPAIR) {
            int p = col - NC;
            a = 0;
            for (;; a++) { int cnt = NC - 1 - a; if (p < cnt) break; p -= cnt; }
            b = a + 1 + p;
            c = 16;
        } else {
            int q = col - NC - NPAIR;
            a = 0;
            for (;; a++) {
                int m = NC - 1 - a;
                int cnt = (m * (m - 1)) >> 1;     // C(m,2)
                if (q < cnt) break;
                q -= cnt;
            }
            b = a + 1;
            for (;; b++) { int cnt = NC - 1 - b; if (q < cnt) break; q -= cnt; }
            c = b + 1 + q;
        }
        stab[col] = (uint32_t)a | ((uint32_t)b << 8) | ((uint32_t)c << 16);
    }

    // dummy operand column: written once, never overwritten by tile loads
    if (t < RTILE) xs[t][16] = 1.0f;
    __syncthreads();

    // ---- Decode this thread's fixed chunk ONCE into register pointers ----
    const bool active = (t < Q4);
    const float* base = &xs[0][0];
    const float *p0 = base, *p1 = base, *p2 = base, *p3 = base,
                *p4 = base, *p5 = base, *p6 = base, *p7 = base,
                *p8 = base, *p9 = base, *pa = base, *pb = base;
    if (active) {
        uint4 pk = reinterpret_cast<const uint4*>(stab)[t];
        p0 = base + ( pk.x        & 255u);
        p1 = base + ((pk.x >>  8) & 255u);
        p2 = base + ( pk.x >> 16        );
        p3 = base + ( pk.y        & 255u);
        p4 = base + ((pk.y >>  8) & 255u);
        p5 = base + ( pk.y >> 16        );
        p6 = base + ( pk.z        & 255u);
        p7 = base + ((pk.z >>  8) & 255u);
        p8 = base + ( pk.z >> 16        );
        p9 = base + ( pk.w        & 255u);
        pa = base + ((pk.w >>  8) & 255u);
        pb = base + ( pk.w >> 16        );
    }

    const int ntiles = (nrows + RTILE - 1) / RTILE;

    for (int tile = blockIdx.x; tile < ntiles; tile += gridDim.x) {
        const int row0 = tile * RTILE;

        __syncthreads();   // xs reuse safety

        // ---- Coalesced tile load: RTILE*16 floats = 64 float4 ----
        if (t < RTILE * NC / 4) {
            const int r = t >> 2;
            if (row0 + r < nrows) {
                float4 v = reinterpret_cast<const float4*>(
                               x + (size_t)row0 * NC)[t];
                *reinterpret_cast<float4*>(&xs[r][(t & 3) << 2]) = v;
            }
        }
        __syncthreads();

        if (!active) continue;

        float4* ob = out4 + (size_t)row0 * Q4 + t;

        if (row0 + RTILE <= nrows) {
            // fast path: full tile, all offsets compile-time immediates
            #pragma unroll
            for (int r = 0; r < RTILE; r++) {
                const int o = r * PAD;
                float4 v;
                v.x = p0[o] * p1[o] * p2[o];
                v.y = p3[o] * p4[o] * p5[o];
                v.z = p6[o] * p7[o] * p8[o];
                v.w = p9[o] * pa[o] * pb[o];
                ob[(size_t)r * Q4] = v;
            }
        } else {
            const int rem = nrows - row0;
            for (int r = 0; r < rem; r++) {
                const int o = r * PAD;
                float4 v;
                v.x = p0[o] * p1[o] * p2[o];
                v.y = p3[o] * p4[o] * p5[o];
                v.z = p6[o] * p7[o] * p8[o];
                v.w = p9[o] * pa[o] * pb[o];
                ob[(size_t)r * Q4] = v;
            }
        }
    }
}

extern "C" void kernel_launch(void* const* d_in, const int* in_sizes, int n_in,
                              void* d_out, int out_size)
{
    const float* x = (const float*)d_in[0];
    const int nrows = in_sizes[0] / NC;

    const int ntiles = (nrows + RTILE - 1) / RTILE;
    int grid = 148 * 10;                 // best-known config (R2)
    if (grid > ntiles) grid = ntiles;

    algebraic_expand_kernel<<<grid, BLK>>>(x, (float4*)d_out, nrows);
}

// round 8
// speedup vs baseline: 1.0816x; 1.0816x over previous
#include <cuda_runtime.h>
#include <stdint.h>

// Algebraic feature expansion:
//   out[:, 0:16]    = x
//   out[:, 16:136]  = pair products  x[a]*x[b]   (lex order)
//   out[:, 136:696] = triple products x[a]*x[b]*x[c] (lex order)
// B=262144 rows, 696 out cols. HBM-store + L1tex co-bound.
//
// v8: R2 skeleton (full 16-row unroll, __stcs, grid 1480, BLK 192) with the
// operand count per output cut from 3 to 2: all 120 pair products per row are
// staged into smem once per tile; triples then read (pair, x[c]) = 2 LDS
// instead of (a,b,c) = 3 LDS. 12 LDS -> 8 LDS and 8 FMUL -> 4 FMUL per chunk,
// and 8 operand pointers instead of 12 (fewer regs than R2).
// Extended smem row: [ x[0..15], 1.0 @16, pad, pairs @20..139 ].

#define NC    16
#define NPAIR 120
#define OUTC  696
#define Q4    174          // OUTC / 4
#define RTILE 16           // rows per tile
#define EXT   140          // floats per extended row (16 x + 1.0 + pad + 120 pairs)
#define POFF  20           // pair region offset within ext row
#define BLK   192          // 6 warps; threads [0,174) compute

__global__ __launch_bounds__(BLK) void algebraic_expand_kernel(
    const float* __restrict__ x,
    float4* __restrict__ out4,
    int nrows)
{
    __shared__ __align__(16) uint32_t stab[OUTC];   // off1 | off2<<16 per out col
    __shared__ __align__(16) uint32_t ptab[NPAIR];  // a | b<<8 per pair
    __shared__ __align__(16) float xs[RTILE][EXT];

    const int t = threadIdx.x;

    // ---- Build tables once ----
    for (int col = t; col < OUTC; col += BLK) {
        int a, b, c;
        uint32_t off1, off2;
        if (col < NC) {
            off1 = (uint32_t)col; off2 = 16u;             // x[a] * 1.0
        } else if (col < NC + NPAIR) {
            int p = col - NC;
            a = 0;
            for (;; a++) { int cnt = NC - 1 - a; if (p < cnt) break; p -= cnt; }
            b = a + 1 + p;
            off1 = (uint32_t)a; off2 = (uint32_t)b;        // x[a] * x[b]
        } else {
            int q = col - NC - NPAIR;
            a = 0;
            for (;; a++) {
                int m = NC - 1 - a;
                int cnt = (m * (m - 1)) >> 1;     // C(m,2)
                if (q < cnt) break;
                q -= cnt;
            }
            b = a + 1;
            for (;; b++) { int cnt = NC - 1 - b; if (q < cnt) break; q -= cnt; }
            c = b + 1 + q;
            // lexicographic pair index of (a,b)
            int pi = a * 15 - ((a * (a - 1)) >> 1) + (b - a - 1);
            off1 = (uint32_t)(POFF + pi); off2 = (uint32_t)c;  // pair * x[c]
        }
        stab[col] = off1 | (off2 << 16);
    }
    for (int p = t; p < NPAIR; p += BLK) {
        int a = 0, pp = p;
        for (;; a++) { int cnt = NC - 1 - a; if (pp < cnt) break; pp -= cnt; }
        int b = a + 1 + pp;
        ptab[p] = (uint32_t)a | ((uint32_t)b << 8);
    }
    // dummy operand: written once, never overwritten
    if (t < RTILE) xs[t][16] = 1.0f;
    __syncthreads();

    // ---- Decode this thread's fixed chunk ONCE into 8 register pointers ----
    const bool active = (t < Q4);
    const float* base = &xs[0][0];
    const float *q0 = base, *q1 = base, *q2 = base, *q3 = base,
                *q4 = base, *q5 = base, *q6 = base, *q7 = base;
    if (active) {
        uint4 pk = reinterpret_cast<const uint4*>(stab)[t];
        q0 = base + (pk.x & 0xffffu);  q1 = base + (pk.x >> 16);
        q2 = base + (pk.y & 0xffffu);  q3 = base + (pk.y >> 16);
        q4 = base + (pk.z & 0xffffu);  q5 = base + (pk.z >> 16);
        q6 = base + (pk.w & 0xffffu);  q7 = base + (pk.w >> 16);
    }

    const int ntiles = (nrows + RTILE - 1) / RTILE;

    for (int tile = blockIdx.x; tile < ntiles; tile += gridDim.x) {
        const int row0 = tile * RTILE;

        __syncthreads();   // xs reuse safety

        // ---- Coalesced tile load: RTILE*16 floats = 64 float4 ----
        if (t < RTILE * NC / 4) {
            const int r = t >> 2;
            if (row0 + r < nrows) {
                float4 v = reinterpret_cast<const float4*>(
                               x + (size_t)row0 * NC)[t];
                *reinterpret_cast<float4*>(&xs[r][(t & 3) << 2]) = v;
            }
        }
        __syncthreads();

        // ---- Stage all pair products: 120 pairs x 16 rows = 1920 items ----
        #pragma unroll
        for (int s = t; s < NPAIR * RTILE; s += BLK) {   // exactly 10 per thread
            const int p = s >> 4;
            const int r = s & 15;
            const uint32_t ab = ptab[p];
            xs[r][POFF + p] = xs[r][ab & 255u] * xs[r][ab >> 8];
        }
        __syncthreads();

        if (!active) continue;

        float4* ob = out4 + (size_t)row0 * Q4 + t;

        if (row0 + RTILE <= nrows) {
            // fast path: full tile, all offsets compile-time immediates
            #pragma unroll
            for (int r = 0; r < RTILE; r++) {
                const int o = r * EXT;
                float4 v;
                v.x = q0[o] * q1[o];
                v.y = q2[o] * q3[o];
                v.z = q4[o] * q5[o];
                v.w = q6[o] * q7[o];
                __stcs(&ob[(size_t)r * Q4], v);
            }
        } else {
            const int rem = nrows - row0;
            for (int r = 0; r < rem; r++) {
                const int o = r * EXT;
                float4 v;
                v.x = q0[o] * q1[o];
                v.y = q2[o] * q3[o];
                v.z = q4[o] * q5[o];
                v.w = q6[o] * q7[o];
                __stcs(&ob[(size_t)r * Q4], v);
            }
        }
    }
}

extern "C" void kernel_launch(void* const* d_in, const int* in_sizes, int n_in,
                              void* d_out, int out_size)
{
    const float* x = (const float*)d_in[0];
    const int nrows = in_sizes[0] / NC;

    const int ntiles = (nrows + RTILE - 1) / RTILE;
    int grid = 148 * 10;                 // best-known config (R2)
    if (grid > ntiles) grid = ntiles;

    algebraic_expand_kernel<<<grid, BLK>>>(x, (float4*)d_out, nrows);
}